// round 16
// baseline (speedup 1.0000x reference)
#include <cuda_runtime.h>

#define TK    2048
#define SL    8          // sub-chunk length
#define NSUB  256        // sub-chunks
#define NCH   64         // chunks of 32 (4 subs)
#define NSUP  16         // supers of 128 (4 chunks)
#define NTHR  256
#define NITER 6
#define NEGV   (-1.0e4f)
#define NEGINF (-1.0e30f)

// XOR swizzle (involution), used only for the prologue ys temp array.
__device__ __forceinline__ int SW1(int t) { return t ^ ((t >> 5) & 31); }
// Transposed (phase-3/phase-1 friendly) layout: thread sc's step-i operand
// lives at i*256+sc -> immediate offsets, bank = sc%32, conflict-free.
__device__ __forceinline__ int GT(int t) { return ((t & 7) << 8) | (t >> 3); }

// ---- dynamic smem layout (bytes) ----
#define OFF_YS1  0        // float[2048]  8192   prologue-only temp (SW1 layout)
#define OFF_LAT1 8192     // float[2048]  8192   combined a, dec1, g-layout
#define OFF_LAT2 16384    // float[2048]  8192   combined a, dec2, g-layout
#define OFF_YPT2 24576    // float[2048]  8192   parity1, g-layout
#define OFF_YPT3 32768    // float[2048]  8192   parity2, g-layout
#define OFF_MSUB 40960    // float[16][256] 16384
#define OFF_MCH  57344    // float[16][64]   4096
#define OFF_MSUP 61440    // float[16][16]   1024
#define OFF_BSA  62464    // float[17*4]      272
#define OFF_BSB  62736    // float[17*4]      272
#define OFF_BCA  63008    // float[65*4]     1040
#define OFF_BCB  64048    // float[65*4]     1040
#define OFF_BSUBA 65088   // float4[256]     4096
#define OFF_BSUBB 69184   // float4[256]     4096
#define OFF_D0   73280    // float2[2048]   16384  (ys, g-dst) for dec0
#define OFF_D1   89664    // float2[2048]   16384  (ys, g-dst) for dec1
#define OFF_ILV  106048   // u16[2048]       4096  raw interleaver
#define OFF_XPK  110144   // u32[64]          256
#define OFF_EMAP 110400   // u8[128]
#define OFF_EST  110528   // u8[132]
#define SMEM_BYTES 110720

extern "C" __global__ void __launch_bounds__(NTHR, 2)
turbo_full_kernel(const int* __restrict__ x_g,
                  const float* __restrict__ n1_g,
                  const float* __restrict__ n2_g,
                  const float* __restrict__ n3_g,
                  const int* __restrict__ ilv_g,
                  float* __restrict__ out_g)
{
    extern __shared__ unsigned char sm[];
    float*  ys1  = (float*)(sm + OFF_YS1);
    float*  LaT1 = (float*)(sm + OFF_LAT1);
    float*  LaT2 = (float*)(sm + OFF_LAT2);
    float*  YpT2 = (float*)(sm + OFF_YPT2);
    float*  YpT3 = (float*)(sm + OFF_YPT3);
    float*  Msub = (float*)(sm + OFF_MSUB);
    float*  Mch  = (float*)(sm + OFF_MCH);
    float*  Msup = (float*)(sm + OFF_MSUP);
    float*  bSA  = (float*)(sm + OFF_BSA);
    float*  bSB  = (float*)(sm + OFF_BSB);
    float*  bCA  = (float*)(sm + OFF_BCA);
    float*  bCB  = (float*)(sm + OFF_BCB);
    float4* bSubA= (float4*)(sm + OFF_BSUBA);
    float4* bSubB= (float4*)(sm + OFF_BSUBB);
    float2* D0   = (float2*)(sm + OFF_D0);
    float2* D1   = (float2*)(sm + OFF_D1);
    unsigned short* ilvp = (unsigned short*)(sm + OFF_ILV);
    unsigned int*   xpk  = (unsigned int*)(sm + OFF_XPK);
    unsigned char*  emap = (unsigned char*)(sm + OFF_EMAP);
    unsigned char*  est  = (unsigned char*)(sm + OFF_EST);

    const int row = blockIdx.x;
    const int tid = threadIdx.x;

    const int*   xr  = x_g  + (size_t)row * TK;
    const float* n1r = n1_g + (size_t)row * TK;
    const float* n2r = n2_g + (size_t)row * TK;
    const float* n3r = n3_g + (size_t)row * TK;
    float*       outr= out_g+ (size_t)row * TK;

    // ---------------- Prologue ----------------
    #pragma unroll
    for (int t = tid; t < TK; t += NTHR) {
        int il = ilv_g[t];
        ilvp[t] = (unsigned short)il;      // raw, natural order
        int u = xr[t];
        unsigned mask = __ballot_sync(0xffffffffu, u != 0);
        if ((t & 31) == 0) xpk[t >> 5] = mask;
        float ys = (2.0f * (float)u - 1.0f) + n1r[t];
        ys1[SW1(t)] = ys;                  // temp for D-table gather
        int g = GT(t);
        LaT1[g] = ys;                      // combined a = ys (La=0 initially)
        YpT2[g] = n2r[t];
        YpT3[g] = n3r[t];
    }
    __syncthreads();
    // Scatter-pair tables: D[g(src)] = (ys at dst's systematic, g(dst)).
    #pragma unroll
    for (int t = tid; t < TK; t += NTHR) {
        int il  = (int)ilvp[t];
        float ysl = ys1[SW1(il)];          // ys at natural position il
        D1[GT(t)]  = make_float2(ysl, __int_as_float(GT(il)));
        D0[GT(il)] = make_float2(ysl, __int_as_float(GT(t)));
    }

    // ---------------- Encoders (chunked state-map scan) ----------------
    if (tid < 128) {
        int e = tid >> 6, cc = tid & 63;
        unsigned m = 0xE4u;              // identity 2-bit state map
        unsigned w0 = xpk[cc];
        int base = cc * 32;
        for (int i = 0; i < 32; i++) {
            unsigned u;
            if (e) { int il = (int)ilvp[base + i];
                     u = (xpk[il >> 5] >> (il & 31)) & 1u; }
            else   { u = (w0 >> i) & 1u; }
            unsigned nm = 0;
            #pragma unroll
            for (int k = 0; k < 4; k++) {
                unsigned s  = (m >> (2 * k)) & 3u;
                unsigned s1 = s >> 1, s2 = s & 1u;
                unsigned a  = u ^ s1 ^ s2;
                nm |= (((a << 1) | s1) << (2 * k));
            }
            m = nm;
        }
        emap[e * 64 + cc] = (unsigned char)m;
    }
    __syncthreads();
    if (tid == 0 || tid == 32) {
        int e = (tid == 32) ? 1 : 0;
        unsigned s = 0;
        for (int c = 0; c < 64; c++) {
            est[e * 65 + c] = (unsigned char)s;
            s = (emap[e * 64 + c] >> (2 * s)) & 3u;
        }
        est[e * 65 + 64] = (unsigned char)s;
    }
    __syncthreads();
    if (tid < 128) {
        int e = tid >> 6, cc = tid & 63;
        unsigned s = est[e * 65 + cc];
        unsigned w0 = xpk[cc];
        int base = cc * 32;
        for (int i = 0; i < 32; i++) {
            int t = base + i;
            unsigned u;
            if (e) { int il = (int)ilvp[t];
                     u = (xpk[il >> 5] >> (il & 31)) & 1u; }
            else   { u = (w0 >> i) & 1u; }
            unsigned s1 = s >> 1, s2 = s & 1u;
            unsigned a  = u ^ s1 ^ s2;
            unsigned p  = a ^ s2;
            float bp = 2.0f * (float)p - 1.0f;
            if (e) YpT3[GT(t)] += bp; else YpT2[GT(t)] += bp;
            s = (a << 1) | s1;
        }
    }
    __syncthreads();

    // ---------------- Turbo iterations ----------------
    for (int it = 0; it < NITER; it++) {
        for (int dec = 0; dec < 2; dec++) {
            const float* La = dec ? LaT2 : LaT1;
            const float* Yp = dec ? YpT3 : YpT2;

            // gammas for this thread's sub-chunk, cached for phase 3
            float GP[SL], GM[SL];

            // ---- Phase 1: batched immediate-offset gamma loads, then
            //      per-sub forward 4x4 matrices (steps 0/1 analytic) ----
            {
                int sc = tid;
                const float* Lap = La + sc;
                const float* Ypp = Yp + sc;
                #pragma unroll
                for (int i = 0; i < SL; i++) {
                    float a  = Lap[i * NSUB];
                    float yp = Ypp[i * NSUB];
                    GP[i] = a + yp; GM[i] = a - yp;
                }
                float gp0 = GP[0], gm0 = GM[0], gp1 = GP[1], gm1 = GM[1];
                float v00 = -gp0-gp1, v01 =  gp0+gm1, v02 = -gp0+gp1, v03 =  gp0-gm1;
                float v10 =  gp0-gp1, v11 = -gp0+gm1, v12 =  gp0+gp1, v13 = -gp0-gm1;
                float v20 =  gm0+gp1, v21 = -gm0-gm1, v22 =  gm0-gp1, v23 = -gm0+gm1;
                float v30 = -gm0+gp1, v31 =  gm0-gm1, v32 = -gm0-gp1, v33 =  gm0+gm1;
                #pragma unroll
                for (int i = 2; i < SL; i++) {
                    float gp = GP[i], gm = GM[i];
                    #define FWD4(A0,A1,A2,A3) { \
                        float _m0 = fmaxf(A0 - gp, A1 + gp); \
                        float _m2 = fmaxf(A0 + gp, A1 - gp); \
                        float _m1 = fmaxf(A2 + gm, A3 - gm); \
                        float _m3 = fmaxf(A2 - gm, A3 + gm); \
                        A0 = _m0; A1 = _m1; A2 = _m2; A3 = _m3; }
                    FWD4(v00, v01, v02, v03)
                    FWD4(v10, v11, v12, v13)
                    FWD4(v20, v21, v22, v23)
                    FWD4(v30, v31, v32, v33)
                    #undef FWD4
                }
                Msub[ 0*NSUB+sc]=v00; Msub[ 1*NSUB+sc]=v01; Msub[ 2*NSUB+sc]=v02; Msub[ 3*NSUB+sc]=v03;
                Msub[ 4*NSUB+sc]=v10; Msub[ 5*NSUB+sc]=v11; Msub[ 6*NSUB+sc]=v12; Msub[ 7*NSUB+sc]=v13;
                Msub[ 8*NSUB+sc]=v20; Msub[ 9*NSUB+sc]=v21; Msub[10*NSUB+sc]=v22; Msub[11*NSUB+sc]=v23;
                Msub[12*NSUB+sc]=v30; Msub[13*NSUB+sc]=v31; Msub[14*NSUB+sc]=v32; Msub[15*NSUB+sc]=v33;
            }
            // 1b reads only the quad's own Msub columns -> warp sync suffices.
            __syncwarp();

            // ---- Phase 1b: compose 4 subs -> chunk matrices (row/thread) ----
            {
                int c = tid >> 2, r = tid & 3;
                const float* M0 = Msub + 4 * c;
                float w0 = M0[(r*4+0)*NSUB], w1 = M0[(r*4+1)*NSUB];
                float w2 = M0[(r*4+2)*NSUB], w3 = M0[(r*4+3)*NSUB];
                #pragma unroll
                for (int m = 1; m < 4; m++) {
                    const float* M = Msub + 4 * c + m;
                    float n0 = fmaxf(fmaxf(w0 + M[ 0*NSUB], w1 + M[ 4*NSUB]),
                                     fmaxf(w2 + M[ 8*NSUB], w3 + M[12*NSUB]));
                    float n1 = fmaxf(fmaxf(w0 + M[ 1*NSUB], w1 + M[ 5*NSUB]),
                                     fmaxf(w2 + M[ 9*NSUB], w3 + M[13*NSUB]));
                    float n2 = fmaxf(fmaxf(w0 + M[ 2*NSUB], w1 + M[ 6*NSUB]),
                                     fmaxf(w2 + M[10*NSUB], w3 + M[14*NSUB]));
                    float n3 = fmaxf(fmaxf(w0 + M[ 3*NSUB], w1 + M[ 7*NSUB]),
                                     fmaxf(w2 + M[11*NSUB], w3 + M[15*NSUB]));
                    w0 = n0; w1 = n1; w2 = n2; w3 = n3;
                }
                Mch[(r*4+0)*NCH + c] = w0; Mch[(r*4+1)*NCH + c] = w1;
                Mch[(r*4+2)*NCH + c] = w2; Mch[(r*4+3)*NCH + c] = w3;
            }
            __syncthreads();

            // ---- Pyramid: threads 0..127, named barriers ----
            if (tid < 128) {
                if (tid < 64) {   // 1c: compose 4 chunks -> super matrices
                    int p = tid >> 2, r = tid & 3;
                    const float* M0 = Mch + 4 * p;
                    float w0 = M0[(r*4+0)*NCH], w1 = M0[(r*4+1)*NCH];
                    float w2 = M0[(r*4+2)*NCH], w3 = M0[(r*4+3)*NCH];
                    #pragma unroll
                    for (int m = 1; m < 4; m++) {
                        const float* M = Mch + 4 * p + m;
                        float n0 = fmaxf(fmaxf(w0 + M[ 0*NCH], w1 + M[ 4*NCH]),
                                         fmaxf(w2 + M[ 8*NCH], w3 + M[12*NCH]));
                        float n1 = fmaxf(fmaxf(w0 + M[ 1*NCH], w1 + M[ 5*NCH]),
                                         fmaxf(w2 + M[ 9*NCH], w3 + M[13*NCH]));
                        float n2 = fmaxf(fmaxf(w0 + M[ 2*NCH], w1 + M[ 6*NCH]),
                                         fmaxf(w2 + M[10*NCH], w3 + M[14*NCH]));
                        float n3 = fmaxf(fmaxf(w0 + M[ 3*NCH], w1 + M[ 7*NCH]),
                                         fmaxf(w2 + M[11*NCH], w3 + M[15*NCH]));
                        w0 = n0; w1 = n1; w2 = n2; w3 = n3;
                    }
                    Msup[(r*4+0)*NSUP + p] = w0; Msup[(r*4+1)*NSUP + p] = w1;
                    Msup[(r*4+2)*NSUP + p] = w2; Msup[(r*4+3)*NSUP + p] = w3;
                }
                asm volatile("bar.sync 1, 128;" ::: "memory");

                // 2: serial super scans (two warps concurrently)
                if (tid == 0) {
                    float v0 = 0.0f, v1 = NEGV, v2 = NEGV, v3 = NEGV;
                    bSA[0] = v0; bSA[1] = v1; bSA[2] = v2; bSA[3] = v3;
                    #pragma unroll 4
                    for (int p = 0; p < NSUP; p++) {
                        const float* M = Msup + p;
                        float s  = v0 + M[0];
                        float w0 = fmaxf(fmaxf(v0 + M[ 0*NSUP], v1 + M[ 4*NSUP]),
                                         fmaxf(v2 + M[ 8*NSUP], v3 + M[12*NSUP]));
                        float w1 = fmaxf(fmaxf(v0 + M[ 1*NSUP], v1 + M[ 5*NSUP]),
                                         fmaxf(v2 + M[ 9*NSUP], v3 + M[13*NSUP]));
                        float w2 = fmaxf(fmaxf(v0 + M[ 2*NSUP], v1 + M[ 6*NSUP]),
                                         fmaxf(v2 + M[10*NSUP], v3 + M[14*NSUP]));
                        float w3 = fmaxf(fmaxf(v0 + M[ 3*NSUP], v1 + M[ 7*NSUP]),
                                         fmaxf(v2 + M[11*NSUP], v3 + M[15*NSUP]));
                        v0 = w0 - s; v1 = w1 - s; v2 = w2 - s; v3 = w3 - s;
                        float* bp = bSA + (p + 1) * 4;
                        bp[0] = v0; bp[1] = v1; bp[2] = v2; bp[3] = v3;
                    }
                } else if (tid == 32) {
                    float v0 = 0.0f, v1 = 0.0f, v2 = 0.0f, v3 = 0.0f;
                    float* be = bSB + NSUP * 4;
                    be[0] = 0.0f; be[1] = 0.0f; be[2] = 0.0f; be[3] = 0.0f;
                    #pragma unroll 4
                    for (int p = NSUP - 1; p >= 0; p--) {
                        const float* M = Msup + p;
                        float s  = v0 + M[0];
                        float w0 = fmaxf(fmaxf(M[ 0*NSUP] + v0, M[ 1*NSUP] + v1),
                                         fmaxf(M[ 2*NSUP] + v2, M[ 3*NSUP] + v3));
                        float w1 = fmaxf(fmaxf(M[ 4*NSUP] + v0, M[ 5*NSUP] + v1),
                                         fmaxf(M[ 6*NSUP] + v2, M[ 7*NSUP] + v3));
                        float w2 = fmaxf(fmaxf(M[ 8*NSUP] + v0, M[ 9*NSUP] + v1),
                                         fmaxf(M[10*NSUP] + v2, M[11*NSUP] + v3));
                        float w3 = fmaxf(fmaxf(M[12*NSUP] + v0, M[13*NSUP] + v1),
                                         fmaxf(M[14*NSUP] + v2, M[15*NSUP] + v3));
                        v0 = w0 - s; v1 = w1 - s; v2 = w2 - s; v3 = w3 - s;
                        float* bp = bSB + p * 4;
                        bp[0] = v0; bp[1] = v1; bp[2] = v2; bp[3] = v3;
                    }
                }
                asm volatile("bar.sync 1, 128;" ::: "memory");

                // 2b: super -> chunk boundaries
                if (tid < 16) {
                    int p = tid;
                    float v0 = bSA[p*4+0], v1 = bSA[p*4+1], v2 = bSA[p*4+2], v3 = bSA[p*4+3];
                    float* bp0 = bCA + (4*p) * 4;
                    bp0[0] = v0; bp0[1] = v1; bp0[2] = v2; bp0[3] = v3;
                    #pragma unroll
                    for (int cl = 0; cl < 3; cl++) {
                        int c = 4*p + cl;
                        const float* M = Mch + c;
                        float s  = v0 + M[0];
                        float w0 = fmaxf(fmaxf(v0 + M[ 0*NCH], v1 + M[ 4*NCH]),
                                         fmaxf(v2 + M[ 8*NCH], v3 + M[12*NCH]));
                        float w1 = fmaxf(fmaxf(v0 + M[ 1*NCH], v1 + M[ 5*NCH]),
                                         fmaxf(v2 + M[ 9*NCH], v3 + M[13*NCH]));
                        float w2 = fmaxf(fmaxf(v0 + M[ 2*NCH], v1 + M[ 6*NCH]),
                                         fmaxf(v2 + M[10*NCH], v3 + M[14*NCH]));
                        float w3 = fmaxf(fmaxf(v0 + M[ 3*NCH], v1 + M[ 7*NCH]),
                                         fmaxf(v2 + M[11*NCH], v3 + M[15*NCH]));
                        v0 = w0 - s; v1 = w1 - s; v2 = w2 - s; v3 = w3 - s;
                        float* bp = bCA + (c + 1) * 4;
                        bp[0] = v0; bp[1] = v1; bp[2] = v2; bp[3] = v3;
                    }
                } else if (tid >= 32 && tid < 48) {
                    int p = tid - 32;
                    float v0 = bSB[(p+1)*4+0], v1 = bSB[(p+1)*4+1];
                    float v2 = bSB[(p+1)*4+2], v3 = bSB[(p+1)*4+3];
                    float* bp4 = bCB + (4*p + 4) * 4;
                    bp4[0] = v0; bp4[1] = v1; bp4[2] = v2; bp4[3] = v3;
                    #pragma unroll
                    for (int cl = 3; cl >= 1; cl--) {
                        int c = 4*p + cl;
                        const float* M = Mch + c;
                        float s  = v0 + M[0];
                        float w0 = fmaxf(fmaxf(M[ 0*NCH] + v0, M[ 1*NCH] + v1),
                                         fmaxf(M[ 2*NCH] + v2, M[ 3*NCH] + v3));
                        float w1 = fmaxf(fmaxf(M[ 4*NCH] + v0, M[ 5*NCH] + v1),
                                         fmaxf(M[ 6*NCH] + v2, M[ 7*NCH] + v3));
                        float w2 = fmaxf(fmaxf(M[ 8*NCH] + v0, M[ 9*NCH] + v1),
                                         fmaxf(M[10*NCH] + v2, M[11*NCH] + v3));
                        float w3 = fmaxf(fmaxf(M[12*NCH] + v0, M[13*NCH] + v1),
                                         fmaxf(M[14*NCH] + v2, M[15*NCH] + v3));
                        v0 = w0 - s; v1 = w1 - s; v2 = w2 - s; v3 = w3 - s;
                        float* bp = bCB + c * 4;
                        bp[0] = v0; bp[1] = v1; bp[2] = v2; bp[3] = v3;
                    }
                }
                asm volatile("bar.sync 1, 128;" ::: "memory");

                // 2c: chunk -> sub boundaries (fwd warps 0-1, bwd warps 2-3)
                if (tid < 64) {
                    int c = tid;
                    float v0 = bCA[c*4+0], v1 = bCA[c*4+1], v2 = bCA[c*4+2], v3 = bCA[c*4+3];
                    bSubA[4*c] = make_float4(v0, v1, v2, v3);
                    #pragma unroll
                    for (int m = 0; m < 3; m++) {
                        const float* M = Msub + 4*c + m;
                        float n0 = fmaxf(fmaxf(v0 + M[ 0*NSUB], v1 + M[ 4*NSUB]),
                                         fmaxf(v2 + M[ 8*NSUB], v3 + M[12*NSUB]));
                        float n1 = fmaxf(fmaxf(v0 + M[ 1*NSUB], v1 + M[ 5*NSUB]),
                                         fmaxf(v2 + M[ 9*NSUB], v3 + M[13*NSUB]));
                        float n2 = fmaxf(fmaxf(v0 + M[ 2*NSUB], v1 + M[ 6*NSUB]),
                                         fmaxf(v2 + M[10*NSUB], v3 + M[14*NSUB]));
                        float n3 = fmaxf(fmaxf(v0 + M[ 3*NSUB], v1 + M[ 7*NSUB]),
                                         fmaxf(v2 + M[11*NSUB], v3 + M[15*NSUB]));
                        v0 = n0; v1 = n1; v2 = n2; v3 = n3;
                        bSubA[4*c + m + 1] = make_float4(v0, v1, v2, v3);
                    }
                } else {
                    int c = tid - 64;
                    float v0 = bCB[(c+1)*4+0], v1 = bCB[(c+1)*4+1];
                    float v2 = bCB[(c+1)*4+2], v3 = bCB[(c+1)*4+3];
                    bSubB[4*c + 3] = make_float4(v0, v1, v2, v3);
                    #pragma unroll
                    for (int m = 3; m >= 1; m--) {
                        const float* M = Msub + 4*c + m;
                        float n0 = fmaxf(fmaxf(M[ 0*NSUB] + v0, M[ 1*NSUB] + v1),
                                         fmaxf(M[ 2*NSUB] + v2, M[ 3*NSUB] + v3));
                        float n1 = fmaxf(fmaxf(M[ 4*NSUB] + v0, M[ 5*NSUB] + v1),
                                         fmaxf(M[ 6*NSUB] + v2, M[ 7*NSUB] + v3));
                        float n2 = fmaxf(fmaxf(M[ 8*NSUB] + v0, M[ 9*NSUB] + v1),
                                         fmaxf(M[10*NSUB] + v2, M[11*NSUB] + v3));
                        float n3 = fmaxf(fmaxf(M[12*NSUB] + v0, M[13*NSUB] + v1),
                                         fmaxf(M[14*NSUB] + v2, M[15*NSUB] + v3));
                        v0 = n0; v1 = n1; v2 = n2; v3 = n3;
                        bSubB[4*c + m - 1] = make_float4(v0, v1, v2, v3);
                    }
                }
            }
            __syncthreads();

            // ---- Phase 3: bwd walk (betas in regs, cached gammas) then
            //      fwd walk with shared a+/-g sums + LLR + scatter ----
            {
                int sc = tid;

                float4 bvec = bSubB[sc];
                float b0 = bvec.x, b1 = bvec.y, b2 = bvec.z, b3 = bvec.w;

                // backward walk: cache exit betas; gammas from registers
                float B0[SL], B1[SL], B2[SL], B3[SL];
                #pragma unroll
                for (int i = SL - 1; i >= 0; i--) {
                    B0[i] = b0; B1[i] = b1; B2[i] = b2; B3[i] = b3;
                    float gp = GP[i], gm = GM[i];
                    float t0p = b2 + gp, t1p = b0 + gp, t2p = b1 + gm, t3p = b3 + gm;
                    float t0m = b0 - gp, t1m = b2 - gp, t2m = b3 - gm, t3m = b1 - gm;
                    b0 = fmaxf(t0m, t0p); b1 = fmaxf(t1m, t1p);
                    b2 = fmaxf(t2m, t2p); b3 = fmaxf(t3m, t3p);
                }

                float4 avec = bSubA[sc];
                float a0 = avec.x, a1 = avec.y, a2 = avec.z, a3 = avec.w;

                // forward walk: shared a+/-g sums feed LLR trees AND advance
                const float2* Dp = dec ? D1 : D0;
                float* LaDst = dec ? LaT1 : LaT2;
                const bool lastout = (dec == 1) && (it == NITER - 1);
                #pragma unroll
                for (int i = 0; i < SL; i++) {
                    float gp = GP[i], gm = GM[i];
                    float s0m = a0 - gp, s0p = a0 + gp;
                    float s1m = a1 - gp, s1p = a1 + gp;
                    float s2m = a2 - gm, s2p = a2 + gm;
                    float s3m = a3 - gm, s3p = a3 + gm;
                    float m1v = fmaxf(fmaxf(s0p + B2[i], s1p + B0[i]),
                                      fmaxf(s2p + B1[i], s3p + B3[i]));
                    float m0v = fmaxf(fmaxf(s0m + B0[i], s1m + B2[i]),
                                      fmaxf(s2m + B3[i], s3m + B1[i]));
                    float llr = m1v - m0v;
                    float ex  = llr - (gp + gm);     // llr - 2*ys - La
                    float2 pr = Dp[i * NSUB + sc];   // (ys, g-dst) conflict-free LDS.64
                    int dw = __float_as_int(pr.y);
                    LaDst[dw] = pr.x + 0.5f * ex;
                    if (lastout) {
                        int dv = ((dw & 255) << 3) | (dw >> 8);  // g -> raw index
                        outr[dv] = llr;
                    }
                    // advance alpha (reuses the shared sums)
                    a0 = fmaxf(s0m, s1p);
                    a2 = fmaxf(s0p, s1m);
                    a1 = fmaxf(s2p, s3m);
                    a3 = fmaxf(s2m, s3p);
                }
            }
            __syncthreads();
        }
    }
}

extern "C" void kernel_launch(void* const* d_in, const int* in_sizes, int n_in,
                              void* d_out, int out_size)
{
    const int*   x  = (const int*)d_in[0];
    const float* n1 = (const float*)d_in[1];
    const float* n2 = (const float*)d_in[2];
    const float* n3 = (const float*)d_in[3];
    const int*   il = (const int*)d_in[4];
    float* out = (float*)d_out;

    int B = in_sizes[0] / TK;

    cudaFuncSetAttribute(turbo_full_kernel,
                         cudaFuncAttributeMaxDynamicSharedMemorySize, SMEM_BYTES);
    turbo_full_kernel<<<B, NTHR, SMEM_BYTES>>>(x, n1, n2, n3, il, out);
}

// round 17
// speedup vs baseline: 1.0266x; 1.0266x over previous
#include <cuda_runtime.h>

#define TK    2048
#define SL    8          // sub-chunk length
#define NSUB  256        // sub-chunks
#define NCH   64         // chunks of 32 (4 subs)
#define NCHP  65         // padded Mch row stride (65 % 32 == 1 -> 2-way max)
#define NSUP  16         // supers of 128 (4 chunks)
#define MSP   17         // padded Msup row stride
#define NTHR  256
#define NITER 6
#define NEGV   (-1.0e4f)
#define NEGINF (-1.0e30f)

// XOR swizzle: stride-1/8/32 smem access all conflict-free. Involution.
__device__ __forceinline__ int SW1(int t) { return t ^ ((t >> 5) & 31); }

// ---- dynamic smem layout (bytes) ----
#define OFF_YS1  0        // float[2048]  8192
#define OFF_YP2  8192     // float[2048]  8192
#define OFF_YP3  16384    // float[2048]  8192
#define OFF_LA1  24576    // float[2048]  8192
#define OFF_LA2  32768    // float[2048]  8192
#define OFF_MSUB 40960    // float[16][256] 16384
#define OFF_MCH  57344    // float[16][65]   4160
#define OFF_MSUP 61504    // float[16][17]   1088
#define OFF_BSA  62592    // float[17*4]      272
#define OFF_BSB  62864    // float[17*4]      272
#define OFF_BCA  63136    // float[65*4]     1040
#define OFF_BCB  64176    // float[65*4]     1040
#define OFF_BSUBA 65216   // float4[256]     4096
#define OFF_BSUBB 69312   // float4[256]     4096
#define OFF_D0   73408    // float2[2048]   16384  (ys, dst) dec0, transposed
#define OFF_D1   89792    // float2[2048]   16384  (ys, dst) dec1
#define OFF_ILV  106176   // u16[2048]       4096  raw interleaver
#define OFF_XPK  110272   // u32[64]          256
#define OFF_EMAP 110528   // u8[128]
#define OFF_EST  110656   // u8[132]
#define SMEM_BYTES 110848

extern "C" __global__ void __launch_bounds__(NTHR, 2)
turbo_full_kernel(const int* __restrict__ x_g,
                  const float* __restrict__ n1_g,
                  const float* __restrict__ n2_g,
                  const float* __restrict__ n3_g,
                  const int* __restrict__ ilv_g,
                  float* __restrict__ out_g)
{
    extern __shared__ unsigned char sm[];
    float*  ys1  = (float*)(sm + OFF_YS1);
    float*  yp2  = (float*)(sm + OFF_YP2);
    float*  yp3  = (float*)(sm + OFF_YP3);
    float*  La1  = (float*)(sm + OFF_LA1);
    float*  La2  = (float*)(sm + OFF_LA2);
    float*  Msub = (float*)(sm + OFF_MSUB);
    float*  Mch  = (float*)(sm + OFF_MCH);
    float*  Msup = (float*)(sm + OFF_MSUP);
    float*  bSA  = (float*)(sm + OFF_BSA);
    float*  bSB  = (float*)(sm + OFF_BSB);
    float*  bCA  = (float*)(sm + OFF_BCA);
    float*  bCB  = (float*)(sm + OFF_BCB);
    float4* bSubA= (float4*)(sm + OFF_BSUBA);
    float4* bSubB= (float4*)(sm + OFF_BSUBB);
    float2* D0   = (float2*)(sm + OFF_D0);
    float2* D1   = (float2*)(sm + OFF_D1);
    unsigned short* ilvp = (unsigned short*)(sm + OFF_ILV);
    unsigned int*   xpk  = (unsigned int*)(sm + OFF_XPK);
    unsigned char*  emap = (unsigned char*)(sm + OFF_EMAP);
    unsigned char*  est  = (unsigned char*)(sm + OFF_EST);

    const int row = blockIdx.x;
    const int tid = threadIdx.x;

    const int*   xr  = x_g  + (size_t)row * TK;
    const float* n1r = n1_g + (size_t)row * TK;
    const float* n2r = n2_g + (size_t)row * TK;
    const float* n3r = n3_g + (size_t)row * TK;
    float*       outr= out_g+ (size_t)row * TK;

    // ---------------- Prologue ----------------
    #pragma unroll
    for (int t = tid; t < TK; t += NTHR) {
        int il = ilv_g[t];
        ilvp[t] = (unsigned short)il;      // raw, natural order
        int u = xr[t];
        unsigned mask = __ballot_sync(0xffffffffu, u != 0);
        if ((t & 31) == 0) xpk[t >> 5] = mask;
        int tw = SW1(t);
        float ys = (2.0f * (float)u - 1.0f) + n1r[t];
        ys1[tw] = ys;
        La1[tw] = ys;          // combined a = ys + 0 (La=0 initially)
        yp2[tw] = n2r[t];
        yp3[tw] = n3r[t];
    }
    __syncthreads();
    // Build scatter-pair tables. Transposed layout g(t) = (t&7)*256 + (t>>3):
    // phase-3 thread sc reads D[i*256 + sc] -> linear, conflict-free LDS.64.
    #pragma unroll
    for (int t = tid; t < TK; t += NTHR) {
        int il  = (int)ilvp[t];
        int ilw = SW1(il);
        float ysl = ys1[ilw];              // systematic at interleaved position t
        int g1 = (t & 7) * 256 + (t >> 3);
        D1[g1] = make_float2(ysl, __int_as_float(ilw));
        int g0 = (il & 7) * 256 + (il >> 3);
        D0[g0] = make_float2(ysl, __int_as_float(SW1(t)));
    }

    // ---------------- Encoders (chunked state-map scan) ----------------
    if (tid < 128) {
        int e = tid >> 6, cc = tid & 63;
        unsigned m = 0xE4u;              // identity 2-bit state map
        unsigned w0 = xpk[cc];
        int base = cc * 32;
        for (int i = 0; i < 32; i++) {
            unsigned u;
            if (e) { int il = (int)ilvp[base + i];
                     u = (xpk[il >> 5] >> (il & 31)) & 1u; }
            else   { u = (w0 >> i) & 1u; }
            unsigned nm = 0;
            #pragma unroll
            for (int k = 0; k < 4; k++) {
                unsigned s  = (m >> (2 * k)) & 3u;
                unsigned s1 = s >> 1, s2 = s & 1u;
                unsigned a  = u ^ s1 ^ s2;
                nm |= (((a << 1) | s1) << (2 * k));
            }
            m = nm;
        }
        emap[e * 64 + cc] = (unsigned char)m;
    }
    __syncthreads();
    if (tid == 0 || tid == 32) {
        int e = (tid == 32) ? 1 : 0;
        unsigned s = 0;
        for (int c = 0; c < 64; c++) {
            est[e * 65 + c] = (unsigned char)s;
            s = (emap[e * 64 + c] >> (2 * s)) & 3u;
        }
        est[e * 65 + 64] = (unsigned char)s;
    }
    __syncthreads();
    if (tid < 128) {
        int e = tid >> 6, cc = tid & 63;
        unsigned s = est[e * 65 + cc];
        unsigned w0 = xpk[cc];
        int base = cc * 32;
        for (int i = 0; i < 32; i++) {
            int t = base + i;
            unsigned u;
            if (e) { int il = (int)ilvp[t];
                     u = (xpk[il >> 5] >> (il & 31)) & 1u; }
            else   { u = (w0 >> i) & 1u; }
            unsigned s1 = s >> 1, s2 = s & 1u;
            unsigned a  = u ^ s1 ^ s2;
            unsigned p  = a ^ s2;
            float bp = 2.0f * (float)p - 1.0f;
            if (e) yp3[SW1(t)] += bp; else yp2[SW1(t)] += bp;
            s = (a << 1) | s1;
        }
    }
    __syncthreads();

    // ---------------- Turbo iterations ----------------
    for (int it = 0; it < NITER; it++) {
        for (int dec = 0; dec < 2; dec++) {
            const float* La = dec ? La2 : La1;
            const float* Yp = dec ? yp3 : yp2;

            // gammas for this thread's sub-chunk, cached for phase 3
            float GP[SL], GM[SL];

            // ---- Phase 1: per-sub forward 4x4 matrices (steps 0/1 analytic) ----
            {
                int sc = tid;
                int base = sc * SL;
                {
                    int tw0 = SW1(base);
                    float a = La[tw0], yp = Yp[tw0];
                    GP[0] = a + yp; GM[0] = a - yp;
                    int tw1 = SW1(base + 1);
                    a = La[tw1]; yp = Yp[tw1];
                    GP[1] = a + yp; GM[1] = a - yp;
                }
                float gp0 = GP[0], gm0 = GM[0], gp1 = GP[1], gm1 = GM[1];
                float v00 = -gp0-gp1, v01 =  gp0+gm1, v02 = -gp0+gp1, v03 =  gp0-gm1;
                float v10 =  gp0-gp1, v11 = -gp0+gm1, v12 =  gp0+gp1, v13 = -gp0-gm1;
                float v20 =  gm0+gp1, v21 = -gm0-gm1, v22 =  gm0-gp1, v23 = -gm0+gm1;
                float v30 = -gm0+gp1, v31 =  gm0-gm1, v32 = -gm0-gp1, v33 =  gm0+gm1;
                #pragma unroll
                for (int i = 2; i < SL; i++) {
                    int tw = SW1(base + i);
                    float a  = La[tw];
                    float yp = Yp[tw];
                    float gp = a + yp, gm = a - yp;
                    GP[i] = gp; GM[i] = gm;
                    #define FWD4(A0,A1,A2,A3) { \
                        float _m0 = fmaxf(A0 - gp, A1 + gp); \
                        float _m2 = fmaxf(A0 + gp, A1 - gp); \
                        float _m1 = fmaxf(A2 + gm, A3 - gm); \
                        float _m3 = fmaxf(A2 - gm, A3 + gm); \
                        A0 = _m0; A1 = _m1; A2 = _m2; A3 = _m3; }
                    FWD4(v00, v01, v02, v03)
                    FWD4(v10, v11, v12, v13)
                    FWD4(v20, v21, v22, v23)
                    FWD4(v30, v31, v32, v33)
                    #undef FWD4
                }
                Msub[ 0*NSUB+sc]=v00; Msub[ 1*NSUB+sc]=v01; Msub[ 2*NSUB+sc]=v02; Msub[ 3*NSUB+sc]=v03;
                Msub[ 4*NSUB+sc]=v10; Msub[ 5*NSUB+sc]=v11; Msub[ 6*NSUB+sc]=v12; Msub[ 7*NSUB+sc]=v13;
                Msub[ 8*NSUB+sc]=v20; Msub[ 9*NSUB+sc]=v21; Msub[10*NSUB+sc]=v22; Msub[11*NSUB+sc]=v23;
                Msub[12*NSUB+sc]=v30; Msub[13*NSUB+sc]=v31; Msub[14*NSUB+sc]=v32; Msub[15*NSUB+sc]=v33;
            }
            // 1b reads only the quad's own Msub columns -> warp sync suffices.
            __syncwarp();

            // ---- Phase 1b: compose 4 subs -> chunk matrices (row/thread) ----
            {
                int c = tid >> 2, r = tid & 3;
                const float* M0 = Msub + 4 * c;
                float w0 = M0[(r*4+0)*NSUB], w1 = M0[(r*4+1)*NSUB];
                float w2 = M0[(r*4+2)*NSUB], w3 = M0[(r*4+3)*NSUB];
                #pragma unroll
                for (int m = 1; m < 4; m++) {
                    const float* M = Msub + 4 * c + m;
                    float n0 = fmaxf(fmaxf(w0 + M[ 0*NSUB], w1 + M[ 4*NSUB]),
                                     fmaxf(w2 + M[ 8*NSUB], w3 + M[12*NSUB]));
                    float n1 = fmaxf(fmaxf(w0 + M[ 1*NSUB], w1 + M[ 5*NSUB]),
                                     fmaxf(w2 + M[ 9*NSUB], w3 + M[13*NSUB]));
                    float n2 = fmaxf(fmaxf(w0 + M[ 2*NSUB], w1 + M[ 6*NSUB]),
                                     fmaxf(w2 + M[10*NSUB], w3 + M[14*NSUB]));
                    float n3 = fmaxf(fmaxf(w0 + M[ 3*NSUB], w1 + M[ 7*NSUB]),
                                     fmaxf(w2 + M[11*NSUB], w3 + M[15*NSUB]));
                    w0 = n0; w1 = n1; w2 = n2; w3 = n3;
                }
                Mch[(r*4+0)*NCHP + c] = w0; Mch[(r*4+1)*NCHP + c] = w1;
                Mch[(r*4+2)*NCHP + c] = w2; Mch[(r*4+3)*NCHP + c] = w3;
            }
            __syncthreads();

            // ---- Pyramid: threads 0..127, named barriers ----
            if (tid < 128) {
                if (tid < 64) {   // 1c: compose 4 chunks -> super matrices
                    int p = tid >> 2, r = tid & 3;
                    const float* M0 = Mch + 4 * p;
                    float w0 = M0[(r*4+0)*NCHP], w1 = M0[(r*4+1)*NCHP];
                    float w2 = M0[(r*4+2)*NCHP], w3 = M0[(r*4+3)*NCHP];
                    #pragma unroll
                    for (int m = 1; m < 4; m++) {
                        const float* M = Mch + 4 * p + m;
                        float n0 = fmaxf(fmaxf(w0 + M[ 0*NCHP], w1 + M[ 4*NCHP]),
                                         fmaxf(w2 + M[ 8*NCHP], w3 + M[12*NCHP]));
                        float n1 = fmaxf(fmaxf(w0 + M[ 1*NCHP], w1 + M[ 5*NCHP]),
                                         fmaxf(w2 + M[ 9*NCHP], w3 + M[13*NCHP]));
                        float n2 = fmaxf(fmaxf(w0 + M[ 2*NCHP], w1 + M[ 6*NCHP]),
                                         fmaxf(w2 + M[10*NCHP], w3 + M[14*NCHP]));
                        float n3 = fmaxf(fmaxf(w0 + M[ 3*NCHP], w1 + M[ 7*NCHP]),
                                         fmaxf(w2 + M[11*NCHP], w3 + M[15*NCHP]));
                        w0 = n0; w1 = n1; w2 = n2; w3 = n3;
                    }
                    Msup[(r*4+0)*MSP + p] = w0; Msup[(r*4+1)*MSP + p] = w1;
                    Msup[(r*4+2)*MSP + p] = w2; Msup[(r*4+3)*MSP + p] = w3;
                }
                asm volatile("bar.sync 1, 128;" ::: "memory");

                // 2: serial super scans (two warps concurrently)
                if (tid == 0) {
                    float v0 = 0.0f, v1 = NEGV, v2 = NEGV, v3 = NEGV;
                    bSA[0] = v0; bSA[1] = v1; bSA[2] = v2; bSA[3] = v3;
                    #pragma unroll 4
                    for (int p = 0; p < NSUP; p++) {
                        const float* M = Msup + p;
                        float s  = v0 + M[0];
                        float w0 = fmaxf(fmaxf(v0 + M[ 0*MSP], v1 + M[ 4*MSP]),
                                         fmaxf(v2 + M[ 8*MSP], v3 + M[12*MSP]));
                        float w1 = fmaxf(fmaxf(v0 + M[ 1*MSP], v1 + M[ 5*MSP]),
                                         fmaxf(v2 + M[ 9*MSP], v3 + M[13*MSP]));
                        float w2 = fmaxf(fmaxf(v0 + M[ 2*MSP], v1 + M[ 6*MSP]),
                                         fmaxf(v2 + M[10*MSP], v3 + M[14*MSP]));
                        float w3 = fmaxf(fmaxf(v0 + M[ 3*MSP], v1 + M[ 7*MSP]),
                                         fmaxf(v2 + M[11*MSP], v3 + M[15*MSP]));
                        v0 = w0 - s; v1 = w1 - s; v2 = w2 - s; v3 = w3 - s;
                        float* bp = bSA + (p + 1) * 4;
                        bp[0] = v0; bp[1] = v1; bp[2] = v2; bp[3] = v3;
                    }
                } else if (tid == 32) {
                    float v0 = 0.0f, v1 = 0.0f, v2 = 0.0f, v3 = 0.0f;
                    float* be = bSB + NSUP * 4;
                    be[0] = 0.0f; be[1] = 0.0f; be[2] = 0.0f; be[3] = 0.0f;
                    #pragma unroll 4
                    for (int p = NSUP - 1; p >= 0; p--) {
                        const float* M = Msup + p;
                        float s  = v0 + M[0];
                        float w0 = fmaxf(fmaxf(M[ 0*MSP] + v0, M[ 1*MSP] + v1),
                                         fmaxf(M[ 2*MSP] + v2, M[ 3*MSP] + v3));
                        float w1 = fmaxf(fmaxf(M[ 4*MSP] + v0, M[ 5*MSP] + v1),
                                         fmaxf(M[ 6*MSP] + v2, M[ 7*MSP] + v3));
                        float w2 = fmaxf(fmaxf(M[ 8*MSP] + v0, M[ 9*MSP] + v1),
                                         fmaxf(M[10*MSP] + v2, M[11*MSP] + v3));
                        float w3 = fmaxf(fmaxf(M[12*MSP] + v0, M[13*MSP] + v1),
                                         fmaxf(M[14*MSP] + v2, M[15*MSP] + v3));
                        v0 = w0 - s; v1 = w1 - s; v2 = w2 - s; v3 = w3 - s;
                        float* bp = bSB + p * 4;
                        bp[0] = v0; bp[1] = v1; bp[2] = v2; bp[3] = v3;
                    }
                }
                asm volatile("bar.sync 1, 128;" ::: "memory");

                // 2b: super -> chunk boundaries
                if (tid < 16) {
                    int p = tid;
                    float v0 = bSA[p*4+0], v1 = bSA[p*4+1], v2 = bSA[p*4+2], v3 = bSA[p*4+3];
                    float* bp0 = bCA + (4*p) * 4;
                    bp0[0] = v0; bp0[1] = v1; bp0[2] = v2; bp0[3] = v3;
                    #pragma unroll
                    for (int cl = 0; cl < 3; cl++) {
                        int c = 4*p + cl;
                        const float* M = Mch + c;
                        float s  = v0 + M[0];
                        float w0 = fmaxf(fmaxf(v0 + M[ 0*NCHP], v1 + M[ 4*NCHP]),
                                         fmaxf(v2 + M[ 8*NCHP], v3 + M[12*NCHP]));
                        float w1 = fmaxf(fmaxf(v0 + M[ 1*NCHP], v1 + M[ 5*NCHP]),
                                         fmaxf(v2 + M[ 9*NCHP], v3 + M[13*NCHP]));
                        float w2 = fmaxf(fmaxf(v0 + M[ 2*NCHP], v1 + M[ 6*NCHP]),
                                         fmaxf(v2 + M[10*NCHP], v3 + M[14*NCHP]));
                        float w3 = fmaxf(fmaxf(v0 + M[ 3*NCHP], v1 + M[ 7*NCHP]),
                                         fmaxf(v2 + M[11*NCHP], v3 + M[15*NCHP]));
                        v0 = w0 - s; v1 = w1 - s; v2 = w2 - s; v3 = w3 - s;
                        float* bp = bCA + (c + 1) * 4;
                        bp[0] = v0; bp[1] = v1; bp[2] = v2; bp[3] = v3;
                    }
                } else if (tid >= 32 && tid < 48) {
                    int p = tid - 32;
                    float v0 = bSB[(p+1)*4+0], v1 = bSB[(p+1)*4+1];
                    float v2 = bSB[(p+1)*4+2], v3 = bSB[(p+1)*4+3];
                    float* bp4 = bCB + (4*p + 4) * 4;
                    bp4[0] = v0; bp4[1] = v1; bp4[2] = v2; bp4[3] = v3;
                    #pragma unroll
                    for (int cl = 3; cl >= 1; cl--) {
                        int c = 4*p + cl;
                        const float* M = Mch + c;
                        float s  = v0 + M[0];
                        float w0 = fmaxf(fmaxf(M[ 0*NCHP] + v0, M[ 1*NCHP] + v1),
                                         fmaxf(M[ 2*NCHP] + v2, M[ 3*NCHP] + v3));
                        float w1 = fmaxf(fmaxf(M[ 4*NCHP] + v0, M[ 5*NCHP] + v1),
                                         fmaxf(M[ 6*NCHP] + v2, M[ 7*NCHP] + v3));
                        float w2 = fmaxf(fmaxf(M[ 8*NCHP] + v0, M[ 9*NCHP] + v1),
                                         fmaxf(M[10*NCHP] + v2, M[11*NCHP] + v3));
                        float w3 = fmaxf(fmaxf(M[12*NCHP] + v0, M[13*NCHP] + v1),
                                         fmaxf(M[14*NCHP] + v2, M[15*NCHP] + v3));
                        v0 = w0 - s; v1 = w1 - s; v2 = w2 - s; v3 = w3 - s;
                        float* bp = bCB + c * 4;
                        bp[0] = v0; bp[1] = v1; bp[2] = v2; bp[3] = v3;
                    }
                }
                asm volatile("bar.sync 1, 128;" ::: "memory");

                // 2c: chunk -> sub boundaries (fwd warps 0-1, bwd warps 2-3)
                if (tid < 64) {
                    int c = tid;
                    float v0 = bCA[c*4+0], v1 = bCA[c*4+1], v2 = bCA[c*4+2], v3 = bCA[c*4+3];
                    bSubA[4*c] = make_float4(v0, v1, v2, v3);
                    #pragma unroll
                    for (int m = 0; m < 3; m++) {
                        const float* M = Msub + 4*c + m;
                        float n0 = fmaxf(fmaxf(v0 + M[ 0*NSUB], v1 + M[ 4*NSUB]),
                                         fmaxf(v2 + M[ 8*NSUB], v3 + M[12*NSUB]));
                        float n1 = fmaxf(fmaxf(v0 + M[ 1*NSUB], v1 + M[ 5*NSUB]),
                                         fmaxf(v2 + M[ 9*NSUB], v3 + M[13*NSUB]));
                        float n2 = fmaxf(fmaxf(v0 + M[ 2*NSUB], v1 + M[ 6*NSUB]),
                                         fmaxf(v2 + M[10*NSUB], v3 + M[14*NSUB]));
                        float n3 = fmaxf(fmaxf(v0 + M[ 3*NSUB], v1 + M[ 7*NSUB]),
                                         fmaxf(v2 + M[11*NSUB], v3 + M[15*NSUB]));
                        v0 = n0; v1 = n1; v2 = n2; v3 = n3;
                        bSubA[4*c + m + 1] = make_float4(v0, v1, v2, v3);
                    }
                } else {
                    int c = tid - 64;
                    float v0 = bCB[(c+1)*4+0], v1 = bCB[(c+1)*4+1];
                    float v2 = bCB[(c+1)*4+2], v3 = bCB[(c+1)*4+3];
                    bSubB[4*c + 3] = make_float4(v0, v1, v2, v3);
                    #pragma unroll
                    for (int m = 3; m >= 1; m--) {
                        const float* M = Msub + 4*c + m;
                        float n0 = fmaxf(fmaxf(M[ 0*NSUB] + v0, M[ 1*NSUB] + v1),
                                         fmaxf(M[ 2*NSUB] + v2, M[ 3*NSUB] + v3));
                        float n1 = fmaxf(fmaxf(M[ 4*NSUB] + v0, M[ 5*NSUB] + v1),
                                         fmaxf(M[ 6*NSUB] + v2, M[ 7*NSUB] + v3));
                        float n2 = fmaxf(fmaxf(M[ 8*NSUB] + v0, M[ 9*NSUB] + v1),
                                         fmaxf(M[10*NSUB] + v2, M[11*NSUB] + v3));
                        float n3 = fmaxf(fmaxf(M[12*NSUB] + v0, M[13*NSUB] + v1),
                                         fmaxf(M[14*NSUB] + v2, M[15*NSUB] + v3));
                        v0 = n0; v1 = n1; v2 = n2; v3 = n3;
                        bSubB[4*c + m - 1] = make_float4(v0, v1, v2, v3);
                    }
                }
            }
            __syncthreads();

            // ---- Phase 3: bwd walk (betas in regs, cached gammas) then
            //      fwd walk with shared a+/-g sums + LLR + scatter ----
            {
                int sc = tid;

                float4 bvec = bSubB[sc];
                float b0 = bvec.x, b1 = bvec.y, b2 = bvec.z, b3 = bvec.w;

                // backward walk: cache exit betas; gammas from registers
                float B0[SL], B1[SL], B2[SL], B3[SL];
                #pragma unroll
                for (int i = SL - 1; i >= 0; i--) {
                    B0[i] = b0; B1[i] = b1; B2[i] = b2; B3[i] = b3;
                    float gp = GP[i], gm = GM[i];
                    float t0p = b2 + gp, t1p = b0 + gp, t2p = b1 + gm, t3p = b3 + gm;
                    float t0m = b0 - gp, t1m = b2 - gp, t2m = b3 - gm, t3m = b1 - gm;
                    b0 = fmaxf(t0m, t0p); b1 = fmaxf(t1m, t1p);
                    b2 = fmaxf(t2m, t2p); b3 = fmaxf(t3m, t3p);
                }

                float4 avec = bSubA[sc];
                float a0 = avec.x, a1 = avec.y, a2 = avec.z, a3 = avec.w;

                // forward walk: shared a+/-g sums feed LLR trees AND advance
                const float2* Dp = dec ? D1 : D0;
                float* LaDst = dec ? La1 : La2;
                const bool lastout = (dec == 1) && (it == NITER - 1);
                #pragma unroll
                for (int i = 0; i < SL; i++) {
                    float gp = GP[i], gm = GM[i];
                    float s0m = a0 - gp, s0p = a0 + gp;
                    float s1m = a1 - gp, s1p = a1 + gp;
                    float s2m = a2 - gm, s2p = a2 + gm;
                    float s3m = a3 - gm, s3p = a3 + gm;
                    float m1v = fmaxf(fmaxf(s0p + B2[i], s1p + B0[i]),
                                      fmaxf(s2p + B1[i], s3p + B3[i]));
                    float m0v = fmaxf(fmaxf(s0m + B0[i], s1m + B2[i]),
                                      fmaxf(s2m + B3[i], s3m + B1[i]));
                    float llr = m1v - m0v;
                    float ex  = llr - (gp + gm);     // llr - 2*ys - La
                    float2 pr = Dp[i * NSUB + sc];   // (ys, dst) conflict-free LDS.64
                    int dw = __float_as_int(pr.y);
                    LaDst[dw] = pr.x + 0.5f * ex;
                    if (lastout) outr[SW1(dw)] = llr;
                    // advance alpha (reuses the shared sums)
                    a0 = fmaxf(s0m, s1p);
                    a2 = fmaxf(s0p, s1m);
                    a1 = fmaxf(s2p, s3m);
                    a3 = fmaxf(s2m, s3p);
                }
            }
            __syncthreads();
        }
    }
}

extern "C" void kernel_launch(void* const* d_in, const int* in_sizes, int n_in,
                              void* d_out, int out_size)
{
    const int*   x  = (const int*)d_in[0];
    const float* n1 = (const float*)d_in[1];
    const float* n2 = (const float*)d_in[2];
    const float* n3 = (const float*)d_in[3];
    const int*   il = (const int*)d_in[4];
    float* out = (float*)d_out;

    int B = in_sizes[0] / TK;

    cudaFuncSetAttribute(turbo_full_kernel,
                         cudaFuncAttributeMaxDynamicSharedMemorySize, SMEM_BYTES);
    turbo_full_kernel<<<B, NTHR, SMEM_BYTES>>>(x, n1, n2, n3, il, out);
}